// round 1
// baseline (speedup 1.0000x reference)
#include <cuda_runtime.h>

#define N_NODES 100000
#define D_IN    128
#define D_H     64
#define D_OUT   16

// Scratch (allocation-free rule: __device__ globals)
__device__ float g_deg [N_NODES];
__device__ float g_dinv[N_NODES];
__device__ float g_hs1 [(size_t)N_NODES * D_H];
__device__ float g_sum1[(size_t)N_NODES * D_H];
__device__ float g_hs2 [(size_t)N_NODES * D_OUT];
__device__ float g_sum2[(size_t)N_NODES * D_OUT];

// ---------------- degree / normalization ----------------

__global__ void k_deg_init() {
    int i = blockIdx.x * blockDim.x + threadIdx.x;
    if (i < N_NODES) g_deg[i] = 1.0f;   // self-loop
}

__global__ void k_deg_count(const int* __restrict__ dst, int E) {
    int i = blockIdx.x * blockDim.x + threadIdx.x;
    if (i < E) atomicAdd(&g_deg[dst[i]], 1.0f);
}

__global__ void k_dinv() {
    int i = blockIdx.x * blockDim.x + threadIdx.x;
    if (i < N_NODES) g_dinv[i] = rsqrtf(g_deg[i]);
}

// ---------------- layer 1 GEMM: hs1 = (x @ W1) * dinv[row]; sum1 = hs1 ----------------
// 64x64 tile, BK=32, 256 threads (16x16), 4x4 register tile.

__global__ __launch_bounds__(256) void k_gemm1(const float* __restrict__ x,
                                               const float* __restrict__ W1) {
    __shared__ float Xs[64][33];
    __shared__ float Ws[32][65];
    const int tid  = threadIdx.x;
    const int tx   = tid & 15;   // output col group (4 cols)
    const int ty   = tid >> 4;   // output row group (4 rows)
    const int row0 = blockIdx.x * 64;

    float acc[4][4];
#pragma unroll
    for (int i = 0; i < 4; i++)
#pragma unroll
        for (int j = 0; j < 4; j++) acc[i][j] = 0.f;

    for (int k0 = 0; k0 < D_IN; k0 += 32) {
        // load X tile (64 rows x 32 k), coalesced along k
#pragma unroll
        for (int l = 0; l < 8; l++) {
            int idx = tid + l * 256;          // 0..2047
            int m = idx >> 5, k = idx & 31;
            int row = row0 + m;
            Xs[m][k] = (row < N_NODES) ? x[(size_t)row * D_IN + k0 + k] : 0.f;
        }
        // load W tile (32 k x 64 n), coalesced along n
#pragma unroll
        for (int l = 0; l < 8; l++) {
            int idx = tid + l * 256;
            int k = idx >> 6, n = idx & 63;
            Ws[k][n] = W1[(size_t)(k0 + k) * D_H + n];
        }
        __syncthreads();
#pragma unroll
        for (int k = 0; k < 32; k++) {
            float a[4], b[4];
#pragma unroll
            for (int i = 0; i < 4; i++) a[i] = Xs[ty * 4 + i][k];
#pragma unroll
            for (int j = 0; j < 4; j++) b[j] = Ws[k][tx * 4 + j];
#pragma unroll
            for (int i = 0; i < 4; i++)
#pragma unroll
                for (int j = 0; j < 4; j++)
                    acc[i][j] = fmaf(a[i], b[j], acc[i][j]);
        }
        __syncthreads();
    }

#pragma unroll
    for (int i = 0; i < 4; i++) {
        int row = row0 + ty * 4 + i;
        if (row < N_NODES) {
            float di = g_dinv[row];
            float4 v;
            v.x = acc[i][0] * di;
            v.y = acc[i][1] * di;
            v.z = acc[i][2] * di;
            v.w = acc[i][3] * di;
            *(float4*)&g_hs1 [(size_t)row * D_H + tx * 4] = v;
            *(float4*)&g_sum1[(size_t)row * D_H + tx * 4] = v;  // self-loop init
        }
    }
}

// ---------------- layer 1 scatter: sum1[dst] += hs1[src] ----------------
// one thread per (edge, 4-float chunk): 16 threads / edge

__global__ __launch_bounds__(256) void k_scatter1(const int* __restrict__ src,
                                                  const int* __restrict__ dst, int E) {
    long long t = (long long)blockIdx.x * blockDim.x + threadIdx.x;
    int e = (int)(t >> 4);
    if (e >= E) return;
    int part = (int)(t & 15);
    int s = src[e], d = dst[e];
    float4 v = *(const float4*)&g_hs1[(size_t)s * D_H + part * 4];
    float* o = &g_sum1[(size_t)d * D_H + part * 4];
    atomicAdd(o + 0, v.x);
    atomicAdd(o + 1, v.y);
    atomicAdd(o + 2, v.z);
    atomicAdd(o + 3, v.w);
}

// ---------------- node kernel: relu(dinv*sum1 + b1) @ W2, scaled; init sum2 ----------------

__global__ __launch_bounds__(256) void k_node2(const float* __restrict__ W2,
                                               const float* __restrict__ b1) {
    __shared__ float W2s[D_H * D_OUT];
    __shared__ float b1s[D_H];
    for (int i = threadIdx.x; i < D_H * D_OUT; i += blockDim.x) W2s[i] = W2[i];
    if (threadIdx.x < D_H) b1s[threadIdx.x] = b1[threadIdx.x];
    __syncthreads();

    int n = blockIdx.x * blockDim.x + threadIdx.x;
    if (n >= N_NODES) return;
    float di = g_dinv[n];

    float acc[D_OUT];
#pragma unroll
    for (int j = 0; j < D_OUT; j++) acc[j] = 0.f;

    const float4* srow = (const float4*)&g_sum1[(size_t)n * D_H];
#pragma unroll
    for (int k4 = 0; k4 < D_H / 4; k4++) {
        float4 sv = srow[k4];
        float v[4];
        v[0] = fmaxf(fmaf(di, sv.x, b1s[k4 * 4 + 0]), 0.f);
        v[1] = fmaxf(fmaf(di, sv.y, b1s[k4 * 4 + 1]), 0.f);
        v[2] = fmaxf(fmaf(di, sv.z, b1s[k4 * 4 + 2]), 0.f);
        v[3] = fmaxf(fmaf(di, sv.w, b1s[k4 * 4 + 3]), 0.f);
#pragma unroll
        for (int c = 0; c < 4; c++) {
            int k = k4 * 4 + c;
#pragma unroll
            for (int j = 0; j < D_OUT; j++)
                acc[j] = fmaf(v[c], W2s[k * D_OUT + j], acc[j]);
        }
    }
#pragma unroll
    for (int j4 = 0; j4 < D_OUT / 4; j4++) {
        float4 o;
        o.x = acc[j4 * 4 + 0] * di;
        o.y = acc[j4 * 4 + 1] * di;
        o.z = acc[j4 * 4 + 2] * di;
        o.w = acc[j4 * 4 + 3] * di;
        *(float4*)&g_hs2 [(size_t)n * D_OUT + j4 * 4] = o;
        *(float4*)&g_sum2[(size_t)n * D_OUT + j4 * 4] = o;  // self-loop init
    }
}

// ---------------- layer 2 scatter: sum2[dst] += hs2[src] ----------------
// one thread per (edge, 4-float chunk): 4 threads / edge

__global__ __launch_bounds__(256) void k_scatter2(const int* __restrict__ src,
                                                  const int* __restrict__ dst, int E) {
    long long t = (long long)blockIdx.x * blockDim.x + threadIdx.x;
    int e = (int)(t >> 2);
    if (e >= E) return;
    int part = (int)(t & 3);
    int s = src[e], d = dst[e];
    float4 v = *(const float4*)&g_hs2[(size_t)s * D_OUT + part * 4];
    float* o = &g_sum2[(size_t)d * D_OUT + part * 4];
    atomicAdd(o + 0, v.x);
    atomicAdd(o + 1, v.y);
    atomicAdd(o + 2, v.z);
    atomicAdd(o + 3, v.w);
}

// ---------------- final: out = dinv * sum2 + b2 ----------------

__global__ __launch_bounds__(256) void k_final(const float* __restrict__ b2,
                                               float* __restrict__ out) {
    int t = blockIdx.x * blockDim.x + threadIdx.x;   // (node, quarter)
    int n = t >> 2;
    if (n >= N_NODES) return;
    int part = t & 3;
    float di = g_dinv[n];
    float4 s = *(const float4*)&g_sum2[(size_t)n * D_OUT + part * 4];
    float4 b = *(const float4*)&b2[part * 4];
    float4 o;
    o.x = fmaf(di, s.x, b.x);
    o.y = fmaf(di, s.y, b.y);
    o.z = fmaf(di, s.z, b.z);
    o.w = fmaf(di, s.w, b.w);
    *(float4*)&out[(size_t)n * D_OUT + part * 4] = o;
}

// ---------------- launch ----------------

extern "C" void kernel_launch(void* const* d_in, const int* in_sizes, int n_in,
                              void* d_out, int out_size) {
    const float* x  = (const float*)d_in[0];
    const int*   ei = (const int*)  d_in[1];
    const float* W1 = (const float*)d_in[2];
    const float* b1 = (const float*)d_in[3];
    const float* W2 = (const float*)d_in[4];
    const float* b2 = (const float*)d_in[5];
    const int E = in_sizes[1] / 2;
    const int* src = ei;
    const int* dst = ei + E;

    k_deg_init <<<(N_NODES + 255) / 256, 256>>>();
    k_deg_count<<<(E + 255) / 256, 256>>>(dst, E);
    k_dinv     <<<(N_NODES + 255) / 256, 256>>>();

    k_gemm1<<<(N_NODES + 63) / 64, 256>>>(x, W1);

    {
        long long items = (long long)E * 16;
        k_scatter1<<<(unsigned)((items + 255) / 256), 256>>>(src, dst, E);
    }

    k_node2<<<(N_NODES + 255) / 256, 256>>>(W2, b1);

    {
        long long items = (long long)E * 4;
        k_scatter2<<<(unsigned)((items + 255) / 256), 256>>>(src, dst, E);
    }

    k_final<<<(N_NODES * 4 + 255) / 256, 256>>>(b2, (float*)d_out);
}

// round 2
// speedup vs baseline: 2.0449x; 2.0449x over previous
#include <cuda_runtime.h>

#define N_NODES 100000
#define E_MAX   1600000
#define D_IN    128
#define D_H     64
#define D_OUT   16

#define SCAN_B  1024
#define SCAN_NB ((N_NODES + SCAN_B - 1) / SCAN_B)   // 98

// ---- scratch (__device__ globals: allocation-free rule) ----
__device__ float g_dinv[N_NODES];
__device__ int   g_cnt [N_NODES];          // in-degree without self-loop
__device__ int   g_off [N_NODES];          // CSR row offsets (exclusive scan of cnt)
__device__ int   g_cur [N_NODES];          // fill cursors
__device__ int   g_csr [E_MAX];            // src indices grouped by dst
__device__ int   g_bsum[SCAN_NB];          // scan block sums
__device__ int   g_boff[SCAN_NB];          // scanned block offsets
__device__ float g_hs1 [(size_t)N_NODES * D_H];
__device__ float g_sum1[(size_t)N_NODES * D_H];
__device__ float g_hs2 [(size_t)N_NODES * D_OUT];

// ================= CSR build =================

__global__ void k_zero_cnt() {
    int i = blockIdx.x * blockDim.x + threadIdx.x;
    if (i < N_NODES) g_cnt[i] = 0;
}

__global__ void k_count(const int* __restrict__ dst, int E) {
    int i = blockIdx.x * blockDim.x + threadIdx.x;
    if (i < E) atomicAdd(&g_cnt[dst[i]], 1);
}

// block-level inclusive scan (Hillis-Steele); also computes dinv = rsqrt(cnt+1)
__global__ __launch_bounds__(SCAN_B) void k_scan1() {
    __shared__ int sh[SCAN_B];
    int i = blockIdx.x * SCAN_B + threadIdx.x;
    int v = (i < N_NODES) ? g_cnt[i] : 0;
    sh[threadIdx.x] = v;
    __syncthreads();
#pragma unroll
    for (int d = 1; d < SCAN_B; d <<= 1) {
        int t = (threadIdx.x >= d) ? sh[threadIdx.x - d] : 0;
        __syncthreads();
        sh[threadIdx.x] += t;
        __syncthreads();
    }
    if (i < N_NODES) {
        g_off[i]  = sh[threadIdx.x] - v;        // exclusive within block
        g_dinv[i] = rsqrtf((float)v + 1.0f);    // deg includes self-loop
    }
    if (threadIdx.x == SCAN_B - 1) g_bsum[blockIdx.x] = sh[SCAN_B - 1];
}

__global__ void k_scan2() {   // single block of 128 scans SCAN_NB(=98) totals
    __shared__ int sh[128];
    int v = (threadIdx.x < SCAN_NB) ? g_bsum[threadIdx.x] : 0;
    sh[threadIdx.x] = v;
    __syncthreads();
#pragma unroll
    for (int d = 1; d < 128; d <<= 1) {
        int t = (threadIdx.x >= d) ? sh[threadIdx.x - d] : 0;
        __syncthreads();
        sh[threadIdx.x] += t;
        __syncthreads();
    }
    if (threadIdx.x < SCAN_NB) g_boff[threadIdx.x] = sh[threadIdx.x] - v;
}

__global__ __launch_bounds__(SCAN_B) void k_scan3() {
    int i = blockIdx.x * SCAN_B + threadIdx.x;
    if (i < N_NODES) {
        g_off[i] += g_boff[blockIdx.x];
        g_cur[i]  = 0;
    }
}

__global__ void k_fill(const int* __restrict__ src, const int* __restrict__ dst, int E) {
    int i = blockIdx.x * blockDim.x + threadIdx.x;
    if (i < E) {
        int d = dst[i];
        int pos = g_off[d] + atomicAdd(&g_cur[d], 1);
        g_csr[pos] = src[i];
    }
}

// ================= layer-1 GEMM: hs1 = (x @ W1) * dinv[row] =================
// 64x64 tile, BK=32, 256 threads, 4x4 register tile, float4 smem access.

__global__ __launch_bounds__(256) void k_gemm1(const float* __restrict__ x,
                                               const float* __restrict__ W1) {
    __shared__ float Xs[32][68];   // k-major: Xs[k][m], 68 keeps float4 alignment
    __shared__ float Ws[32][68];   // Ws[k][n]
    const int tid  = threadIdx.x;
    const int tx   = tid & 15;     // 4 output cols
    const int ty   = tid >> 4;     // 4 output rows
    const int row0 = blockIdx.x * 64;

    float acc[4][4];
#pragma unroll
    for (int i = 0; i < 4; i++)
#pragma unroll
        for (int j = 0; j < 4; j++) acc[i][j] = 0.f;

    for (int k0 = 0; k0 < D_IN; k0 += 32) {
#pragma unroll
        for (int l = 0; l < 8; l++) {          // X tile: 64 m x 32 k, coalesced on k
            int idx = tid + l * 256;
            int m = idx >> 5, k = idx & 31;
            int row = row0 + m;
            Xs[k][m] = (row < N_NODES) ? x[(size_t)row * D_IN + k0 + k] : 0.f;
        }
#pragma unroll
        for (int l = 0; l < 8; l++) {          // W tile: 32 k x 64 n, coalesced on n
            int idx = tid + l * 256;
            int k = idx >> 6, n = idx & 63;
            Ws[k][n] = W1[(size_t)(k0 + k) * D_H + n];
        }
        __syncthreads();
#pragma unroll
        for (int k = 0; k < 32; k++) {
            float4 a4 = *(const float4*)&Xs[k][ty * 4];
            float4 b4 = *(const float4*)&Ws[k][tx * 4];
            float a[4] = {a4.x, a4.y, a4.z, a4.w};
            float b[4] = {b4.x, b4.y, b4.z, b4.w};
#pragma unroll
            for (int i = 0; i < 4; i++)
#pragma unroll
                for (int j = 0; j < 4; j++)
                    acc[i][j] = fmaf(a[i], b[j], acc[i][j]);
        }
        __syncthreads();
    }

#pragma unroll
    for (int i = 0; i < 4; i++) {
        int row = row0 + ty * 4 + i;
        if (row < N_NODES) {
            float di = g_dinv[row];
            float4 v = {acc[i][0] * di, acc[i][1] * di, acc[i][2] * di, acc[i][3] * di};
            *(float4*)&g_hs1[(size_t)row * D_H + tx * 4] = v;
        }
    }
}

// ================= layer-1 aggregation (gather): sum1[n] = hs1[n] + sum_{s in N(n)} hs1[s] =================
// 16 threads per node, each owns one float4 chunk of the 64-dim row.

__global__ __launch_bounds__(256) void k_agg1() {
    long long t = (long long)blockIdx.x * blockDim.x + threadIdx.x;
    int n = (int)(t >> 4);
    if (n >= N_NODES) return;
    int part = (int)(t & 15);

    const float4* base = (const float4*)g_hs1;
    float4 acc = base[(size_t)n * 16 + part];              // self-loop term
    int off = g_off[n], cnt = g_cnt[n];

    int i = 0;
    for (; i + 4 <= cnt; i += 4) {                         // MLP=4 over neighbor rows
        int s0 = g_csr[off + i + 0];
        int s1 = g_csr[off + i + 1];
        int s2 = g_csr[off + i + 2];
        int s3 = g_csr[off + i + 3];
        float4 v0 = base[(size_t)s0 * 16 + part];
        float4 v1 = base[(size_t)s1 * 16 + part];
        float4 v2 = base[(size_t)s2 * 16 + part];
        float4 v3 = base[(size_t)s3 * 16 + part];
        acc.x += v0.x + v1.x + v2.x + v3.x;
        acc.y += v0.y + v1.y + v2.y + v3.y;
        acc.z += v0.z + v1.z + v2.z + v3.z;
        acc.w += v0.w + v1.w + v2.w + v3.w;
    }
    for (; i < cnt; i++) {
        int s = g_csr[off + i];
        float4 v = base[(size_t)s * 16 + part];
        acc.x += v.x; acc.y += v.y; acc.z += v.z; acc.w += v.w;
    }
    *(float4*)&g_sum1[(size_t)n * D_H + part * 4] = acc;
}

// ================= node kernel: hs2 = (relu(dinv*sum1 + b1) @ W2) * dinv =================

__global__ __launch_bounds__(256) void k_node2(const float* __restrict__ W2,
                                               const float* __restrict__ b1) {
    __shared__ float W2s[D_H * D_OUT];
    __shared__ float b1s[D_H];
    for (int i = threadIdx.x; i < D_H * D_OUT; i += blockDim.x) W2s[i] = W2[i];
    if (threadIdx.x < D_H) b1s[threadIdx.x] = b1[threadIdx.x];
    __syncthreads();

    int n = blockIdx.x * blockDim.x + threadIdx.x;
    if (n >= N_NODES) return;
    float di = g_dinv[n];

    float acc[D_OUT];
#pragma unroll
    for (int j = 0; j < D_OUT; j++) acc[j] = 0.f;

    const float4* srow = (const float4*)&g_sum1[(size_t)n * D_H];
#pragma unroll
    for (int k4 = 0; k4 < D_H / 4; k4++) {
        float4 sv = srow[k4];
        float v[4];
        v[0] = fmaxf(fmaf(di, sv.x, b1s[k4 * 4 + 0]), 0.f);
        v[1] = fmaxf(fmaf(di, sv.y, b1s[k4 * 4 + 1]), 0.f);
        v[2] = fmaxf(fmaf(di, sv.z, b1s[k4 * 4 + 2]), 0.f);
        v[3] = fmaxf(fmaf(di, sv.w, b1s[k4 * 4 + 3]), 0.f);
#pragma unroll
        for (int c = 0; c < 4; c++) {
            int k = k4 * 4 + c;
#pragma unroll
            for (int j = 0; j < D_OUT; j++)
                acc[j] = fmaf(v[c], W2s[k * D_OUT + j], acc[j]);
        }
    }
#pragma unroll
    for (int j4 = 0; j4 < D_OUT / 4; j4++) {
        float4 o = {acc[j4 * 4 + 0] * di, acc[j4 * 4 + 1] * di,
                    acc[j4 * 4 + 2] * di, acc[j4 * 4 + 3] * di};
        *(float4*)&g_hs2[(size_t)n * D_OUT + j4 * 4] = o;
    }
}

// ================= layer-2 aggregation + epilogue: out = dinv * (hs2[n] + sum hs2[s]) + b2 =================
// 4 threads per node (16 floats).

__global__ __launch_bounds__(256) void k_agg2(const float* __restrict__ b2,
                                              float* __restrict__ out) {
    long long t = (long long)blockIdx.x * blockDim.x + threadIdx.x;
    int n = (int)(t >> 2);
    if (n >= N_NODES) return;
    int part = (int)(t & 3);

    const float4* base = (const float4*)g_hs2;
    float4 acc = base[(size_t)n * 4 + part];               // self-loop term
    int off = g_off[n], cnt = g_cnt[n];

    int i = 0;
    for (; i + 4 <= cnt; i += 4) {
        int s0 = g_csr[off + i + 0];
        int s1 = g_csr[off + i + 1];
        int s2 = g_csr[off + i + 2];
        int s3 = g_csr[off + i + 3];
        float4 v0 = base[(size_t)s0 * 4 + part];
        float4 v1 = base[(size_t)s1 * 4 + part];
        float4 v2 = base[(size_t)s2 * 4 + part];
        float4 v3 = base[(size_t)s3 * 4 + part];
        acc.x += v0.x + v1.x + v2.x + v3.x;
        acc.y += v0.y + v1.y + v2.y + v3.y;
        acc.z += v0.z + v1.z + v2.z + v3.z;
        acc.w += v0.w + v1.w + v2.w + v3.w;
    }
    for (; i < cnt; i++) {
        int s = g_csr[off + i];
        float4 v = base[(size_t)s * 4 + part];
        acc.x += v.x; acc.y += v.y; acc.z += v.z; acc.w += v.w;
    }

    float di = g_dinv[n];
    float4 bb = *(const float4*)&b2[part * 4];
    float4 o = {fmaf(di, acc.x, bb.x), fmaf(di, acc.y, bb.y),
                fmaf(di, acc.z, bb.z), fmaf(di, acc.w, bb.w)};
    *(float4*)&out[(size_t)n * D_OUT + part * 4] = o;
}

// ================= launch =================

extern "C" void kernel_launch(void* const* d_in, const int* in_sizes, int n_in,
                              void* d_out, int out_size) {
    const float* x  = (const float*)d_in[0];
    const int*   ei = (const int*)  d_in[1];
    const float* W1 = (const float*)d_in[2];
    const float* b1 = (const float*)d_in[3];
    const float* W2 = (const float*)d_in[4];
    const float* b2 = (const float*)d_in[5];
    const int E = in_sizes[1] / 2;
    const int* src = ei;
    const int* dst = ei + E;

    // CSR build
    k_zero_cnt<<<(N_NODES + 255) / 256, 256>>>();
    k_count   <<<(E + 255) / 256, 256>>>(dst, E);
    k_scan1   <<<SCAN_NB, SCAN_B>>>();
    k_scan2   <<<1, 128>>>();
    k_scan3   <<<SCAN_NB, SCAN_B>>>();
    k_fill    <<<(E + 255) / 256, 256>>>(src, dst, E);

    // layer 1
    k_gemm1<<<(N_NODES + 63) / 64, 256>>>(x, W1);
    {
        long long items = (long long)N_NODES * 16;
        k_agg1<<<(unsigned)((items + 255) / 256), 256>>>();
    }

    // layer 2
    k_node2<<<(N_NODES + 255) / 256, 256>>>(W2, b1);
    {
        long long items = (long long)N_NODES * 4;
        k_agg2<<<(unsigned)((items + 255) / 256), 256>>>(b2, (float*)d_out);
    }
}

// round 3
// speedup vs baseline: 2.0935x; 1.0237x over previous
#include <cuda_runtime.h>

#define N_NODES 100000
#define E_MAX   1600000
#define D_IN    128
#define D_H     64
#define D_OUT   16

#define SCAN_B  1024
#define SCAN_NB ((N_NODES + SCAN_B - 1) / SCAN_B)   // 98

// ---- scratch (__device__ globals: allocation-free rule) ----
// g_cnt / g_cur are re-zeroed by the LAST reader each run (warp-program-order
// safe), so no explicit zeroing kernel is needed; they start zeroed at load.
__device__ float g_dinv[N_NODES];
__device__ int   g_cnt [N_NODES];          // in-degree without self-loop
__device__ int   g_off [N_NODES];          // CSR row offsets
__device__ int   g_cur [N_NODES];          // fill cursors
__device__ int   g_csr [E_MAX];            // src ids grouped by dst
__device__ int   g_bsum[SCAN_NB];          // per-block scan totals
__device__ float g_hs1 [(size_t)N_NODES * D_H];
__device__ float g_hs2 [(size_t)N_NODES * D_OUT];

// ================= CSR build =================

__global__ void k_count(const int* __restrict__ dst, int E) {
    int i = blockIdx.x * blockDim.x + threadIdx.x;
    if (i < E) atomicAdd(&g_cnt[dst[i]], 1);
}

// block-level scan of g_cnt -> g_off (exclusive within block); also dinv.
__global__ __launch_bounds__(SCAN_B) void k_scan1() {
    __shared__ int sh[SCAN_B];
    int i = blockIdx.x * SCAN_B + threadIdx.x;
    int v = (i < N_NODES) ? g_cnt[i] : 0;
    sh[threadIdx.x] = v;
    __syncthreads();
#pragma unroll
    for (int d = 1; d < SCAN_B; d <<= 1) {
        int t = (threadIdx.x >= d) ? sh[threadIdx.x - d] : 0;
        __syncthreads();
        sh[threadIdx.x] += t;
        __syncthreads();
    }
    if (i < N_NODES) {
        g_off[i]  = sh[threadIdx.x] - v;
        g_dinv[i] = rsqrtf((float)v + 1.0f);   // deg includes self-loop
    }
    if (threadIdx.x == SCAN_B - 1) g_bsum[blockIdx.x] = sh[SCAN_B - 1];
}

// each block computes its own prefix of g_bsum (98 values) and adds it.
__global__ __launch_bounds__(SCAN_B) void k_scan3() {
    __shared__ int wsum[SCAN_B / 32];
    __shared__ int sboff;
    int tid = threadIdx.x;
    if (tid < 128) {
        int v = (tid < blockIdx.x) ? g_bsum[tid] : 0;   // blockIdx.x <= 97 < 128
#pragma unroll
        for (int d = 16; d; d >>= 1) v += __shfl_xor_sync(0xffffffffu, v, d);
        if ((tid & 31) == 0) wsum[tid >> 5] = v;
    }
    __syncthreads();
    if (tid == 0) sboff = wsum[0] + wsum[1] + wsum[2] + wsum[3];
    __syncthreads();
    int i = blockIdx.x * SCAN_B + tid;
    if (i < N_NODES) g_off[i] += sboff;
}

__global__ void k_fill(const int* __restrict__ src, const int* __restrict__ dst, int E) {
    int i = blockIdx.x * blockDim.x + threadIdx.x;
    if (i < E) {
        int d = dst[i];
        int pos = g_off[d] + atomicAdd(&g_cur[d], 1);
        g_csr[pos] = src[i];
    }
}

// ================= layer-1 GEMM: hs1 = (x @ W1) * dinv[row] =================
// 128x64 tile, BK=32, 256 threads, 8x4 register tile.

__global__ __launch_bounds__(256) void k_gemm1(const float* __restrict__ x,
                                               const float* __restrict__ W1) {
    __shared__ float Xs[128][33];   // m-major, pad 33: conflict-free both ways
    __shared__ float Ws[32][68];    // k-major, float4-aligned rows
    const int tid  = threadIdx.x;
    const int tx   = tid & 15;      // 4 output cols
    const int ty   = tid >> 4;      // 8 output rows
    const int row0 = blockIdx.x * 128;

    float acc[8][4];
#pragma unroll
    for (int i = 0; i < 8; i++)
#pragma unroll
        for (int j = 0; j < 4; j++) acc[i][j] = 0.f;

    for (int k0 = 0; k0 < D_IN; k0 += 32) {
#pragma unroll
        for (int l = 0; l < 16; l++) {         // X: 128m x 32k, coalesced on k
            int idx = tid + l * 256;
            int m = idx >> 5, k = idx & 31;
            int row = row0 + m;
            Xs[m][k] = (row < N_NODES) ? x[(size_t)row * D_IN + k0 + k] : 0.f;
        }
#pragma unroll
        for (int l = 0; l < 8; l++) {          // W: 32k x 64n, coalesced on n
            int idx = tid + l * 256;
            int k = idx >> 6, n = idx & 63;
            Ws[k][n] = W1[(size_t)(k0 + k) * D_H + n];
        }
        __syncthreads();
#pragma unroll
        for (int k = 0; k < 32; k++) {
            float4 b4 = *(const float4*)&Ws[k][tx * 4];
            float b[4] = {b4.x, b4.y, b4.z, b4.w};
            float a[8];
#pragma unroll
            for (int i = 0; i < 8; i++) a[i] = Xs[ty * 8 + i][k];
#pragma unroll
            for (int i = 0; i < 8; i++)
#pragma unroll
                for (int j = 0; j < 4; j++)
                    acc[i][j] = fmaf(a[i], b[j], acc[i][j]);
        }
        __syncthreads();
    }

#pragma unroll
    for (int i = 0; i < 8; i++) {
        int row = row0 + ty * 8 + i;
        if (row < N_NODES) {
            float di = g_dinv[row];
            float4 v = {acc[i][0] * di, acc[i][1] * di, acc[i][2] * di, acc[i][3] * di};
            *(float4*)&g_hs1[(size_t)row * D_H + tx * 4] = v;
        }
    }
}

// ================= fused layer-1 aggregation + relu + GEMV(W2) =================
// block = 256 threads = 16 nodes x 16 lanes. Phase 1: CSR gather into smem
// (indices loaded once per edge, broadcast via shfl). Phase 2: 64x16 GEMV.
// Grid is exactly N_NODES/16 — no tail divergence.

__global__ __launch_bounds__(256) void k_agg_node(const float* __restrict__ b1,
                                                  const float* __restrict__ W2) {
    __shared__ float sh [16][68];   // relu'd 64-dim rows
    __shared__ float W2t[16][68];   // W2t[j][k] = W2[k][j]

    const int tid  = threadIdx.x;
    const int part = tid & 15;
    const int nl   = tid >> 4;          // node within block (0..15)
    const int n    = blockIdx.x * 16 + nl;
    const int lane = tid & 31;
    const int gb   = lane & 16;         // 16-lane group base within warp
    const unsigned gmask = 0xFFFFu << gb;

#pragma unroll
    for (int idx = tid; idx < D_H * D_OUT; idx += 256) {
        int k = idx >> 4, j = idx & 15;
        W2t[j][k] = W2[idx];
    }

    const int off = g_off[n];
    const int cnt = g_cnt[n];
    if (part == 0) g_cur[n] = 0;        // reset cursor for next run (last reader was k_fill)

    const float4* base = (const float4*)g_hs1;
    float4 acc = base[(size_t)n * 16 + part];          // self-loop term

    for (int i = 0; i < cnt; i += 16) {
        int idx = (i + part < cnt) ? g_csr[off + i + part] : -1;
#pragma unroll
        for (int j = 0; j < 16; j++) {
            int s = __shfl_sync(gmask, idx, gb + j);
            if (s >= 0) {
                float4 v = base[(size_t)s * 16 + part];
                acc.x += v.x; acc.y += v.y; acc.z += v.z; acc.w += v.w;
            }
        }
    }

    const float di = g_dinv[n];
    float4 bb = *(const float4*)&b1[part * 4];
    float4 r;
    r.x = fmaxf(fmaf(di, acc.x, bb.x), 0.f);
    r.y = fmaxf(fmaf(di, acc.y, bb.y), 0.f);
    r.z = fmaxf(fmaf(di, acc.z, bb.z), 0.f);
    r.w = fmaxf(fmaf(di, acc.w, bb.w), 0.f);
    *(float4*)&sh[nl][part * 4] = r;
    __syncthreads();

    // Phase 2: this thread computes output feature j=part for node n.
    float o = 0.f;
#pragma unroll
    for (int k4 = 0; k4 < D_H / 4; k4++) {
        float4 a4 = *(const float4*)&sh [nl]  [k4 * 4];
        float4 w4 = *(const float4*)&W2t[part][k4 * 4];
        o = fmaf(a4.x, w4.x, o);
        o = fmaf(a4.y, w4.y, o);
        o = fmaf(a4.z, w4.z, o);
        o = fmaf(a4.w, w4.w, o);
    }
    g_hs2[(size_t)n * D_OUT + part] = o * di;
}

// ================= layer-2 aggregation + epilogue =================
// 4 lanes per node; indices shfl-broadcast within 4-lane groups.

__global__ __launch_bounds__(256) void k_agg2(const float* __restrict__ b2,
                                              float* __restrict__ out) {
    long long t = (long long)blockIdx.x * blockDim.x + threadIdx.x;
    int n = (int)(t >> 2);
    const int valid = (n < N_NODES);
    if (!valid) n = N_NODES - 1;        // clamp: no early return (shfl safety)
    const int part = (int)(t & 3);
    const int lane = threadIdx.x & 31;
    const int gb4  = lane & ~3;
    const unsigned gmask = 0xFu << gb4;

    const int off = g_off[n];
    const int cnt = g_cnt[n];

    const float4* base = (const float4*)g_hs2;
    float4 acc = base[(size_t)n * 4 + part];           // self-loop term

    for (int i = 0; i < cnt; i += 4) {
        int idx = (i + part < cnt) ? g_csr[off + i + part] : -1;
#pragma unroll
        for (int j = 0; j < 4; j++) {
            int s = __shfl_sync(gmask, idx, gb4 + j);
            if (s >= 0) {
                float4 v = base[(size_t)s * 4 + part];
                acc.x += v.x; acc.y += v.y; acc.z += v.z; acc.w += v.w;
            }
        }
    }

    // reset cnt for next run: every lane of this warp already loaded its cnt
    // (program order), and only the true owner writes.
    if (valid && part == 0) g_cnt[n] = 0;

    if (valid) {
        float di = g_dinv[n];
        float4 bb = *(const float4*)&b2[part * 4];
        float4 o = {fmaf(di, acc.x, bb.x), fmaf(di, acc.y, bb.y),
                    fmaf(di, acc.z, bb.z), fmaf(di, acc.w, bb.w)};
        *(float4*)&out[(size_t)n * D_OUT + part * 4] = o;
    }
}

// ================= launch =================

extern "C" void kernel_launch(void* const* d_in, const int* in_sizes, int n_in,
                              void* d_out, int out_size) {
    const float* x  = (const float*)d_in[0];
    const int*   ei = (const int*)  d_in[1];
    const float* b1 = (const float*)d_in[3];
    const float* W1 = (const float*)d_in[2];
    const float* W2 = (const float*)d_in[4];
    const float* b2 = (const float*)d_in[5];
    const int E = in_sizes[1] / 2;
    const int* src = ei;
    const int* dst = ei + E;

    // CSR build (g_cnt/g_cur arrive zeroed: zero-init at load, re-zeroed by
    // k_agg_node / k_agg2 at the end of every run)
    k_count<<<(E + 255) / 256, 256>>>(dst, E);
    k_scan1<<<SCAN_NB, SCAN_B>>>();
    k_scan3<<<SCAN_NB, SCAN_B>>>();
    k_fill <<<(E + 255) / 256, 256>>>(src, dst, E);

    // layer 1
    k_gemm1   <<<(N_NODES + 127) / 128, 256>>>(x, W1);
    k_agg_node<<<N_NODES / 16, 256>>>(b1, W2);           // 100000/16 = 6250 exact

    // layer 2 + epilogue
    k_agg2<<<(N_NODES * 4 + 255) / 256, 256>>>(b2, (float*)d_out);
}

// round 4
// speedup vs baseline: 2.1162x; 1.0109x over previous
#include <cuda_runtime.h>

#define N_NODES 100000
#define E_MAX   1600000
#define D_IN    128
#define D_H     64
#define D_OUT   16

#define SCAN_B  1024
#define SCAN_NB ((N_NODES + SCAN_B - 1) / SCAN_B)   // 98

// ---- packed f32x2 helpers (sm_103a dual-lane fp32 pipe) ----
#define FFMA2(d, a, b, c) \
    asm("fma.rn.f32x2 %0, %1, %2, %3;" : "=l"(d) : "l"(a), "l"(b), "l"(c))
#define FADD2(d, a, b) \
    asm("add.rn.f32x2 %0, %1, %2;" : "=l"(d) : "l"(a), "l"(b))

__device__ __forceinline__ unsigned long long pack2(float lo, float hi) {
    unsigned long long r;
    asm("mov.b64 %0, {%1, %2};" : "=l"(r) : "f"(lo), "f"(hi));
    return r;
}
__device__ __forceinline__ void unpack2(unsigned long long v, float& lo, float& hi) {
    asm("mov.b64 {%0, %1}, %2;" : "=f"(lo), "=f"(hi) : "l"(v));
}

// ---- scratch (__device__ globals: allocation-free rule) ----
// g_cnt arrives zeroed (zero-init at load; re-zeroed by k_agg2 every run).
__device__ float g_dinv[N_NODES];
__device__ int   g_cnt [N_NODES];
__device__ int   g_off [N_NODES];
__device__ int   g_cur [N_NODES];          // fill cursor, re-seeded to g_off by k_scan3
__device__ int   g_csr [E_MAX];
__device__ int   g_bsum[SCAN_NB];
__device__ float g_hs1 [(size_t)N_NODES * D_H];
__device__ float g_hs2 [(size_t)N_NODES * D_OUT];

// ================= CSR build =================

__global__ void k_count(const int* __restrict__ dst, int E) {
    int b = (blockIdx.x * blockDim.x + threadIdx.x) * 4;
    if (b + 3 < E && ((E & 3) == 0)) {
        int4 d = *(const int4*)&dst[b];
        atomicAdd(&g_cnt[d.x], 1);
        atomicAdd(&g_cnt[d.y], 1);
        atomicAdd(&g_cnt[d.z], 1);
        atomicAdd(&g_cnt[d.w], 1);
    } else {
#pragma unroll
        for (int j = 0; j < 4; j++)
            if (b + j < E) atomicAdd(&g_cnt[dst[b + j]], 1);
    }
}

// warp-shuffle block scan of g_cnt -> g_off (exclusive in block); also dinv.
__global__ __launch_bounds__(SCAN_B) void k_scan1() {
    __shared__ int ws[SCAN_B / 32];
    const int tid = threadIdx.x, lane = tid & 31, warp = tid >> 5;
    int i = blockIdx.x * SCAN_B + tid;
    int v = (i < N_NODES) ? g_cnt[i] : 0;
    int x = v;
#pragma unroll
    for (int d = 1; d < 32; d <<= 1) {
        int t = __shfl_up_sync(0xffffffffu, x, d);
        if (lane >= d) x += t;
    }
    if (lane == 31) ws[warp] = x;
    __syncthreads();
    if (warp == 0) {
        int y = ws[lane];
#pragma unroll
        for (int d = 1; d < 32; d <<= 1) {
            int t = __shfl_up_sync(0xffffffffu, y, d);
            if (lane >= d) y += t;
        }
        ws[lane] = y;
    }
    __syncthreads();
    int excl = x - v + (warp ? ws[warp - 1] : 0);
    if (i < N_NODES) {
        g_off[i]  = excl;
        g_dinv[i] = rsqrtf((float)v + 1.0f);
    }
    if (tid == 0) g_bsum[blockIdx.x] = ws[SCAN_B / 32 - 1];
}

// add prefix of block sums; seed cursors.
__global__ __launch_bounds__(SCAN_B) void k_scan3() {
    __shared__ int wsum[4];
    __shared__ int sboff;
    int tid = threadIdx.x;
    if (tid < 128) {
        int v = (tid < blockIdx.x) ? g_bsum[tid] : 0;   // blockIdx.x <= 97
#pragma unroll
        for (int d = 16; d; d >>= 1) v += __shfl_xor_sync(0xffffffffu, v, d);
        if ((tid & 31) == 0) wsum[tid >> 5] = v;
    }
    __syncthreads();
    if (tid == 0) sboff = wsum[0] + wsum[1] + wsum[2] + wsum[3];
    __syncthreads();
    int i = blockIdx.x * SCAN_B + tid;
    if (i < N_NODES) {
        int o = g_off[i] + sboff;
        g_off[i] = o;
        g_cur[i] = o;       // cursor starts at row offset
    }
}

__global__ void k_fill(const int* __restrict__ src, const int* __restrict__ dst, int E) {
    int b = (blockIdx.x * blockDim.x + threadIdx.x) * 4;
    if (b + 3 < E && ((E & 3) == 0)) {
        int4 s = *(const int4*)&src[b];
        int4 d = *(const int4*)&dst[b];
        g_csr[atomicAdd(&g_cur[d.x], 1)] = s.x;
        g_csr[atomicAdd(&g_cur[d.y], 1)] = s.y;
        g_csr[atomicAdd(&g_cur[d.z], 1)] = s.z;
        g_csr[atomicAdd(&g_cur[d.w], 1)] = s.w;
    } else {
#pragma unroll
        for (int j = 0; j < 4; j++)
            if (b + j < E) g_csr[atomicAdd(&g_cur[dst[b + j]], 1)] = src[b + j];
    }
}

// ================= layer-1 GEMM: hs1 = (x @ W1) * dinv[row] =================
// 128x64 tile, BK=32, 256 threads, 8x4 thread tile, packed f32x2 FMA.
// Xs k-major (row stride 130 floats: 8B-aligned rows, 2-way STS conflict only).
// Wd holds (w,w) duplicated uint64, stride 17 -> conflict-free LDS.64.

__global__ __launch_bounds__(256) void k_gemm1(const float* __restrict__ x,
                                               const float* __restrict__ W1) {
    __shared__ __align__(16) float Xs[32][130];
    __shared__ unsigned long long Wd[32][68];
    const int tid  = threadIdx.x;
    const int tx   = tid & 15;      // 4 output cols
    const int ty   = tid >> 4;      // 8 output rows (4 row-pairs)
    const int row0 = blockIdx.x * 128;

    unsigned long long acc[4][4];   // [row-pair][col]
#pragma unroll
    for (int i = 0; i < 4; i++)
#pragma unroll
        for (int j = 0; j < 4; j++) acc[i][j] = 0ull;

    for (int k0 = 0; k0 < D_IN; k0 += 32) {
#pragma unroll
        for (int l = 0; l < 16; l++) {         // X: 128m x 32k, gmem coalesced on k
            int idx = tid + l * 256;
            int m = idx >> 5, k = idx & 31;
            int row = row0 + m;
            Xs[k][m] = (row < N_NODES) ? x[(size_t)row * D_IN + k0 + k] : 0.f;
        }
#pragma unroll
        for (int l = 0; l < 8; l++) {          // W: 32k x 64n, duplicated-pack
            int idx = tid + l * 256;
            int k = idx >> 6, n = idx & 63;
            float w = W1[(size_t)(k0 + k) * D_H + n];
            Wd[k][(n & 3) * 17 + (n >> 2)] = pack2(w, w);
        }
        __syncthreads();
#pragma unroll
        for (int k = 0; k < 32; k++) {
            const unsigned long long* ap =
                (const unsigned long long*)&Xs[k][ty * 8];
            unsigned long long a0 = ap[0], a1 = ap[1], a2 = ap[2], a3 = ap[3];
            unsigned long long b0 = Wd[k][0 * 17 + tx];
            unsigned long long b1 = Wd[k][1 * 17 + tx];
            unsigned long long b2 = Wd[k][2 * 17 + tx];
            unsigned long long b3 = Wd[k][3 * 17 + tx];
            FFMA2(acc[0][0], a0, b0, acc[0][0]);
            FFMA2(acc[0][1], a0, b1, acc[0][1]);
            FFMA2(acc[0][2], a0, b2, acc[0][2]);
            FFMA2(acc[0][3], a0, b3, acc[0][3]);
            FFMA2(acc[1][0], a1, b0, acc[1][0]);
            FFMA2(acc[1][1], a1, b1, acc[1][1]);
            FFMA2(acc[1][2], a1, b2, acc[1][2]);
            FFMA2(acc[1][3], a1, b3, acc[1][3]);
            FFMA2(acc[2][0], a2, b0, acc[2][0]);
            FFMA2(acc[2][1], a2, b1, acc[2][1]);
            FFMA2(acc[2][2], a2, b2, acc[2][2]);
            FFMA2(acc[2][3], a2, b3, acc[2][3]);
            FFMA2(acc[3][0], a3, b0, acc[3][0]);
            FFMA2(acc[3][1], a3, b1, acc[3][1]);
            FFMA2(acc[3][2], a3, b2, acc[3][2]);
            FFMA2(acc[3][3], a3, b3, acc[3][3]);
        }
        __syncthreads();
    }

#pragma unroll
    for (int i = 0; i < 4; i++) {
        float r0[4], r1[4];
#pragma unroll
        for (int j = 0; j < 4; j++) unpack2(acc[i][j], r0[j], r1[j]);
        int rowA = row0 + ty * 8 + 2 * i;
        int rowB = rowA + 1;
        if (rowA < N_NODES) {
            float di = g_dinv[rowA];
            float4 v = {r0[0] * di, r0[1] * di, r0[2] * di, r0[3] * di};
            *(float4*)&g_hs1[(size_t)rowA * D_H + tx * 4] = v;
        }
        if (rowB < N_NODES) {
            float di = g_dinv[rowB];
            float4 v = {r1[0] * di, r1[1] * di, r1[2] * di, r1[3] * di};
            *(float4*)&g_hs1[(size_t)rowB * D_H + tx * 4] = v;
        }
    }
}

// ================= fused layer-1 aggregation + relu + GEMV(W2) =================
// block = 256 threads = 16 nodes x 16 lanes; indices shfl-broadcast.

__global__ __launch_bounds__(256) void k_agg_node(const float* __restrict__ b1,
                                                  const float* __restrict__ W2) {
    __shared__ float sh [16][68];
    __shared__ float W2t[16][68];   // W2t[j][k] = W2[k][j]

    const int tid  = threadIdx.x;
    const int part = tid & 15;
    const int nl   = tid >> 4;
    const int n    = blockIdx.x * 16 + nl;
    const int lane = tid & 31;
    const int gb   = lane & 16;
    const unsigned gmask = 0xFFFFu << gb;

#pragma unroll
    for (int idx = tid; idx < D_H * D_OUT; idx += 256) {
        int k = idx >> 4, j = idx & 15;
        W2t[j][k] = W2[idx];
    }

    const int off = g_off[n];
    const int cnt = g_cnt[n];

    const ulonglong2* base = (const ulonglong2*)g_hs1;
    ulonglong2 acc = base[(size_t)n * 16 + part];          // self-loop term

    for (int i = 0; i < cnt; i += 16) {
        int idx = (i + part < cnt) ? g_csr[off + i + part] : -1;
#pragma unroll
        for (int j = 0; j < 16; j++) {
            int s = __shfl_sync(gmask, idx, gb + j);
            if (s >= 0) {
                ulonglong2 v = base[(size_t)s * 16 + part];
                FADD2(acc.x, acc.x, v.x);
                FADD2(acc.y, acc.y, v.y);
            }
        }
    }

    float a0, a1, a2, a3;
    unpack2(acc.x, a0, a1);
    unpack2(acc.y, a2, a3);
    const float di = g_dinv[n];
    float4 bb = *(const float4*)&b1[part * 4];
    float4 r;
    r.x = fmaxf(fmaf(di, a0, bb.x), 0.f);
    r.y = fmaxf(fmaf(di, a1, bb.y), 0.f);
    r.z = fmaxf(fmaf(di, a2, bb.z), 0.f);
    r.w = fmaxf(fmaf(di, a3, bb.w), 0.f);
    *(float4*)&sh[nl][part * 4] = r;
    __syncthreads();

    float o = 0.f;
#pragma unroll
    for (int k4 = 0; k4 < D_H / 4; k4++) {
        float4 v4 = *(const float4*)&sh [nl]  [k4 * 4];
        float4 w4 = *(const float4*)&W2t[part][k4 * 4];
        o = fmaf(v4.x, w4.x, o);
        o = fmaf(v4.y, w4.y, o);
        o = fmaf(v4.z, w4.z, o);
        o = fmaf(v4.w, w4.w, o);
    }
    g_hs2[(size_t)n * D_OUT + part] = o * di;
}

// ================= layer-2 aggregation + epilogue =================
// 4 lanes per node; resets g_cnt for the next run.

__global__ __launch_bounds__(256) void k_agg2(const float* __restrict__ b2,
                                              float* __restrict__ out) {
    long long t = (long long)blockIdx.x * blockDim.x + threadIdx.x;
    int n = (int)(t >> 2);
    const int valid = (n < N_NODES);
    if (!valid) n = N_NODES - 1;        // clamp (shfl safety)
    const int part = (int)(t & 3);
    const int lane = threadIdx.x & 31;
    const int gb4  = lane & ~3;
    const unsigned gmask = 0xFu << gb4;

    const int off = g_off[n];
    const int cnt = g_cnt[n];

    const ulonglong2* base = (const ulonglong2*)g_hs2;
    ulonglong2 acc = base[(size_t)n * 4 + part];           // self-loop term

    for (int i = 0; i < cnt; i += 4) {
        int idx = (i + part < cnt) ? g_csr[off + i + part] : -1;
#pragma unroll
        for (int j = 0; j < 4; j++) {
            int s = __shfl_sync(gmask, idx, gb4 + j);
            if (s >= 0) {
                ulonglong2 v = base[(size_t)s * 4 + part];
                FADD2(acc.x, acc.x, v.x);
                FADD2(acc.y, acc.y, v.y);
            }
        }
    }

    if (valid && part == 0) g_cnt[n] = 0;   // reset for next run (after read)

    if (valid) {
        float a0, a1, a2, a3;
        unpack2(acc.x, a0, a1);
        unpack2(acc.y, a2, a3);
        float di = g_dinv[n];
        float4 bb = *(const float4*)&b2[part * 4];
        float4 o = {fmaf(di, a0, bb.x), fmaf(di, a1, bb.y),
                    fmaf(di, a2, bb.z), fmaf(di, a3, bb.w)};
        *(float4*)&out[(size_t)n * D_OUT + part * 4] = o;
    }
}

// ================= launch =================

extern "C" void kernel_launch(void* const* d_in, const int* in_sizes, int n_in,
                              void* d_out, int out_size) {
    const float* x  = (const float*)d_in[0];
    const int*   ei = (const int*)  d_in[1];
    const float* W1 = (const float*)d_in[2];
    const float* b1 = (const float*)d_in[3];
    const float* W2 = (const float*)d_in[4];
    const float* b2 = (const float*)d_in[5];
    const int E = in_sizes[1] / 2;
    const int* src = ei;
    const int* dst = ei + E;

    int egrid4 = (E / 4 + 255) / 256 + 1;   // 4 edges/thread

    // CSR build
    k_count<<<egrid4, 256>>>(dst, E);
    k_scan1<<<SCAN_NB, SCAN_B>>>();
    k_scan3<<<SCAN_NB, SCAN_B>>>();
    k_fill <<<egrid4, 256>>>(src, dst, E);

    // layer 1
    k_gemm1   <<<(N_NODES + 127) / 128, 256>>>(x, W1);
    k_agg_node<<<N_NODES / 16, 256>>>(b1, W2);           // 100000/16 exact

    // layer 2 + epilogue
    k_agg2<<<(N_NODES * 4 + 255) / 256, 256>>>(b2, (float*)d_out);
}